// round 2
// baseline (speedup 1.0000x reference)
#include <cuda_runtime.h>
#include <cuda_fp16.h>
#include <cstdint>

#define DI __device__ __forceinline__

// ---------------- problem dims ----------------
constexpr int BB   = 8;
constexpr int CIN  = 512;
constexpr int HW   = 1024;
constexpr int NH   = 8;
constexpr int DH   = 32;    // head dim
constexpr int OQKV = 768;
constexpr int DV   = 256;
constexpr int COUT = 512;

// ---------------- scratch layout ----------------
constexpr size_t align256(size_t x) { return (x + 255) & ~(size_t)255; }
constexpr size_t SZ_XT     = (size_t)BB * HW * CIN * 2;          // [b][p][c] fp16
constexpr size_t SZ_WQKV   = (size_t)OQKV * CIN * 2;
constexpr size_t SZ_BQKV   = (size_t)OQKV * 4;
constexpr size_t SZ_WATTN  = (size_t)COUT * DV * 2;
constexpr size_t SZ_QT     = (size_t)BB * NH * HW * DH * 2;      // [z][p][d]
constexpr size_t SZ_KT     = SZ_QT;
constexpr size_t SZ_V      = SZ_QT;                              // [z][d][p]
constexpr size_t SZ_AFT    = (size_t)BB * HW * DV * 2;           // [b][p][c]
constexpr size_t SZ_LOG    = (size_t)64 * HW * HW * 2;           // fp16
constexpr size_t SZ_WEI    = SZ_LOG;

constexpr size_t OFF_XT    = 0;
constexpr size_t OFF_WQKV  = align256(OFF_XT    + SZ_XT);
constexpr size_t OFF_BQKV  = align256(OFF_WQKV  + SZ_WQKV);
constexpr size_t OFF_WATTN = align256(OFF_BQKV  + SZ_BQKV);
constexpr size_t OFF_QT    = align256(OFF_WATTN + SZ_WATTN);
constexpr size_t OFF_KT    = align256(OFF_QT    + SZ_QT);
constexpr size_t OFF_V     = align256(OFF_KT    + SZ_KT);
constexpr size_t OFF_AFT   = align256(OFF_V     + SZ_V);
constexpr size_t OFF_LOG   = align256(OFF_AFT   + SZ_AFT);
constexpr size_t OFF_WEI   = align256(OFF_LOG   + SZ_LOG);
constexpr size_t OFF_END   = align256(OFF_WEI   + SZ_WEI);

__device__ __align__(1024) unsigned char g_scratch[OFF_END];

// ---------------- mma helpers ----------------
DI uint32_t smem_u32(const void* p) { return (uint32_t)__cvta_generic_to_shared(p); }

DI void ldmx4(uint32_t* r, uint32_t a) {
    asm volatile("ldmatrix.sync.aligned.m8n8.x4.shared.b16 {%0,%1,%2,%3}, [%4];\n"
                 : "=r"(r[0]), "=r"(r[1]), "=r"(r[2]), "=r"(r[3]) : "r"(a));
}

DI void mma16816(float* c, const uint32_t* a, const uint32_t* b) {
    asm volatile(
        "mma.sync.aligned.m16n8k16.row.col.f32.f16.f16.f32 "
        "{%0,%1,%2,%3}, {%4,%5,%6,%7}, {%8,%9}, {%0,%1,%2,%3};\n"
        : "+f"(c[0]), "+f"(c[1]), "+f"(c[2]), "+f"(c[3])
        : "r"(a[0]), "r"(a[1]), "r"(a[2]), "r"(a[3]), "r"(b[0]), "r"(b[1]));
}

// ---------------- converts ----------------
__global__ void k_conv_wqkv(const float* __restrict__ w, const float* __restrict__ b,
                            __half* __restrict__ wh, float* __restrict__ bh) {
    int i = blockIdx.x * 256 + threadIdx.x;
    constexpr float SC = 0.17677669529663689f; // 32^-0.5 folded into q rows
    if (i < OQKV * CIN) wh[i] = __float2half(w[i] * (i < 256 * CIN ? SC : 1.f));
    if (i < OQKV)       bh[i] = b[i] * (i < 256 ? SC : 1.f);
}

__global__ void k_conv_wattn(const float* __restrict__ w, __half* __restrict__ wh) {
    int i = blockIdx.x * 256 + threadIdx.x;
    if (i < COUT * DV) wh[i] = __float2half(w[i]);
}

// x [b][c][p] fp32 -> XT [b][p][c] fp16  (tiled transpose)
__global__ void k_xT(const float* __restrict__ x, __half* __restrict__ xt) {
    __shared__ float t[32][33];
    int b = blockIdx.z, p0 = blockIdx.x * 32, c0 = blockIdx.y * 32;
    int tx = threadIdx.x, ty = threadIdx.y;
    const float* xp = x + ((long)b * CIN + c0) * HW + p0;
#pragma unroll
    for (int i = 0; i < 32; i += 8) t[ty + i][tx] = xp[(long)(ty + i) * HW + tx];
    __syncthreads();
    __half* d = xt + ((long)b * HW + p0) * CIN + c0;
#pragma unroll
    for (int i = 0; i < 32; i += 8) d[(long)(ty + i) * CIN + tx] = __float2half(t[tx][ty + i]);
}

// ---------------- templated HMMA GEMM ----------------
// C[m][n] = sum_k A[m][k] * B[n][k]   (A, B both k-contiguous row-major)
// EPI 0: plain fp16 C      EPI 1: qkv scatter (+bias, q/k -> [z][p][d], v -> [z][d][p])
// EPI 2: attn scramble+transpose -> AFT[b][p][c]      EPI 3: fp32 + bias
template <int BM, int BN, int BK, int WM, int WN, int NT, int EPI>
__global__ void __launch_bounds__(NT) gemm_k(
    const __half* __restrict__ A, const __half* __restrict__ Bg,
    void* __restrict__ Cg, const float* __restrict__ bias,
    __half* __restrict__ aux1, __half* __restrict__ aux2,
    int K, int lda, int ldb, int ldc, long sA, long sB, long sC)
{
    constexpr int PAD = 8;
    __shared__ __half As[BM][BK + PAD];
    __shared__ __half Bs[BN][BK + PAD];

    const int z  = blockIdx.z;
    const int m0 = blockIdx.y * BM;
    const int n0 = blockIdx.x * BN;
    const __half* Ap = A  + (long)z * sA + (long)m0 * lda;
    const __half* Bp = Bg + (long)z * sB + (long)n0 * ldb;

    const int tid = threadIdx.x, lane = tid & 31, warp = tid >> 5;
    constexpr int WGM   = BM / WM;
    constexpr int MT    = WM / 16;
    constexpr int NTL   = WN / 8;
    const int wm = warp % WGM, wn = warp / WGM;

    float acc[MT][NTL][4];
#pragma unroll
    for (int a = 0; a < MT; a++)
#pragma unroll
        for (int b = 0; b < NTL; b++)
#pragma unroll
            for (int c = 0; c < 4; c++) acc[a][b][c] = 0.f;

    constexpr int KV = BK / 8;                 // uint4 per row
    constexpr int AV = BM * BK / 8, BV = BN * BK / 8;

    for (int k0 = 0; k0 < K; k0 += BK) {
#pragma unroll
        for (int i = 0; i < AV / NT; i++) {
            int idx = tid + i * NT;
            int r = idx / KV, cv = idx % KV;
            *(uint4*)&As[r][cv * 8] = *(const uint4*)&Ap[(long)r * lda + k0 + cv * 8];
        }
#pragma unroll
        for (int i = 0; i < BV / NT; i++) {
            int idx = tid + i * NT;
            int r = idx / KV, cv = idx % KV;
            *(uint4*)&Bs[r][cv * 8] = *(const uint4*)&Bp[(long)r * ldb + k0 + cv * 8];
        }
        __syncthreads();
#pragma unroll
        for (int ks = 0; ks < BK; ks += 16) {
            uint32_t af[MT][4];
#pragma unroll
            for (int mt = 0; mt < MT; mt++)
                ldmx4(af[mt], smem_u32(&As[wm * WM + mt * 16 + (lane & 15)][ks + (lane >> 4) * 8]));
            uint32_t bf[NTL][2];
#pragma unroll
            for (int np = 0; np < NTL / 2; np++) {
                uint32_t r[4];
                ldmx4(r, smem_u32(&Bs[wn * WN + np * 16 + (lane & 15)][ks + (lane >> 4) * 8]));
                bf[np * 2][0] = r[0]; bf[np * 2][1] = r[2];
                bf[np * 2 + 1][0] = r[1]; bf[np * 2 + 1][1] = r[3];
            }
#pragma unroll
            for (int mt = 0; mt < MT; mt++)
#pragma unroll
                for (int nt = 0; nt < NTL; nt++)
                    mma16816(acc[mt][nt], af[mt], bf[nt]);
        }
        __syncthreads();
    }

    // epilogue
#pragma unroll
    for (int mt = 0; mt < MT; mt++)
#pragma unroll
        for (int nt = 0; nt < NTL; nt++)
#pragma unroll
            for (int i = 0; i < 4; i++) {
                int m = m0 + wm * WM + mt * 16 + (lane >> 2) + ((i >> 1) << 3);
                int n = n0 + wn * WN + nt * 8 + ((lane & 3) << 1) + (i & 1);
                float v = acc[mt][nt][i];
                if constexpr (EPI == 0) {
                    ((__half*)Cg)[(long)z * sC + (long)m * ldc + n] = __float2half(v);
                } else if constexpr (EPI == 1) {
                    v += bias[m];
                    int r = m >> 8, rr = m & 255, nh = rr >> 5, d = rr & 31;
                    __half hv = __float2half(v);
                    long zi = (long)(z * NH + nh);
                    if (r == 0)      ((__half*)Cg)[(zi * HW + n) * DH + d] = hv;  // qT
                    else if (r == 1) aux1[(zi * HW + n) * DH + d] = hv;           // kT
                    else             aux2[(zi * DH + d) * HW + n] = hv;           // v
                } else if constexpr (EPI == 2) {
                    int b = z >> 3, nh = z & 7;
                    int j = m * DH + n;            // q*32 + d
                    int c2 = j >> 10, p = j & 1023;
                    ((__half*)Cg)[((long)b * HW + p) * DV + nh * DH + c2] = __float2half(v);
                } else {
                    ((float*)Cg)[(long)z * sC + (long)m * ldc + n] = v + bias[m];
                }
            }
}

// ---------------- head-axis softmax (axis = n over 8 heads) ----------------
__global__ void k_softmax(const __half2* __restrict__ L, __half2* __restrict__ W) {
    int i = blockIdx.x * 256 + threadIdx.x;          // 8 << 19 total
    int b = i >> 19;
    int s = i & ((1 << 19) - 1);
    long base = ((long)(b * NH) << 19) + s;
    float2 l[8];
    float m0 = -1e30f, m1 = -1e30f;
#pragma unroll
    for (int n = 0; n < 8; n++) {
        l[n] = __half22float2(L[base + ((long)n << 19)]);
        m0 = fmaxf(m0, l[n].x); m1 = fmaxf(m1, l[n].y);
    }
    float s0 = 0.f, s1 = 0.f;
#pragma unroll
    for (int n = 0; n < 8; n++) {
        l[n].x = __expf(l[n].x - m0); l[n].y = __expf(l[n].y - m1);
        s0 += l[n].x; s1 += l[n].y;
    }
    float r0 = 1.f / s0, r1 = 1.f / s1;
#pragma unroll
    for (int n = 0; n < 8; n++)
        W[base + ((long)n << 19)] = __floats2half2_rn(l[n].x * r0, l[n].y * r1);
}

// ---------------- launch ----------------
extern "C" void kernel_launch(void* const* d_in, const int* in_sizes, int n_in,
                              void* d_out, int out_size)
{
    const float* x      = (const float*)d_in[0];
    const float* w_qkv  = (const float*)d_in[1];
    const float* b_qkv  = (const float*)d_in[2];
    const float* w_attn = (const float*)d_in[3];
    const float* b_attn = (const float*)d_in[4];
    float* out = (float*)d_out;

    unsigned char* s = nullptr;
    cudaGetSymbolAddress((void**)&s, g_scratch);
    __half* XT    = (__half*)(s + OFF_XT);
    __half* WQKV  = (__half*)(s + OFF_WQKV);
    float*  BQKV  = (float*) (s + OFF_BQKV);
    __half* WATTN = (__half*)(s + OFF_WATTN);
    __half* QT    = (__half*)(s + OFF_QT);
    __half* KT    = (__half*)(s + OFF_KT);
    __half* V     = (__half*)(s + OFF_V);
    __half* AFT   = (__half*)(s + OFF_AFT);
    __half* LOG   = (__half*)(s + OFF_LOG);
    __half* WEI   = (__half*)(s + OFF_WEI);

    // converts
    k_conv_wqkv <<<(OQKV * CIN + 255) / 256, 256>>>(w_qkv, b_qkv, WQKV, BQKV);
    k_conv_wattn<<<(COUT * DV + 255) / 256, 256>>>(w_attn, WATTN);
    k_xT<<<dim3(HW / 32, CIN / 32, BB), dim3(32, 8)>>>(x, XT);

    // QKV: per b, [768x512] x [512x1024]; scatter q/k/v (+bias, q-scale folded)
    gemm_k<128, 128, 32, 64, 32, 256, 1><<<dim3(HW / 128, OQKV / 128, BB), 256>>>(
        WQKV, XT, QT, BQKV, KT, V, CIN, CIN, CIN, 0, 0L, (long)HW * CIN, 0L);

    // logits: per z=(b,n), [1024x32] x [32x1024] -> fp16
    gemm_k<128, 128, 32, 64, 32, 256, 0><<<dim3(HW / 128, HW / 128, 64), 256>>>(
        QT, KT, LOG, nullptr, nullptr, nullptr, DH, DH, DH, HW,
        (long)HW * DH, (long)HW * DH, (long)HW * HW);

    // softmax over head axis
    k_softmax<<<(8 << 19) / 256, 256>>>((const __half2*)LOG, (__half2*)WEI);

    // attn: per z, [1024x1024] x [1024x32]^T; epilogue writes scrambled+transposed AFT
    gemm_k<128, 32, 32, 32, 32, 128, 2><<<dim3(1, HW / 128, 64), 128>>>(
        WEI, V, AFT, nullptr, nullptr, nullptr, HW, HW, HW, 0,
        (long)HW * HW, (long)DH * HW, 0L);

    // output projection: per b, [512x256] x [256x1024] + bias -> fp32
    gemm_k<128, 128, 32, 64, 32, 256, 3><<<dim3(HW / 128, COUT / 128, BB), 256>>>(
        WATTN, AFT, out, b_attn, nullptr, nullptr, DV, DV, DV, HW,
        0L, (long)HW * DV, (long)COUT * HW);
}

// round 3
// speedup vs baseline: 1.8021x; 1.8021x over previous
#include <cuda_runtime.h>
#include <cuda_fp16.h>
#include <cstdint>

#define DI __device__ __forceinline__

// ---------------- problem dims ----------------
constexpr int BB   = 8;
constexpr int CIN  = 512;
constexpr int HW   = 1024;
constexpr int NH   = 8;
constexpr int DH   = 32;    // head dim
constexpr int OQKV = 768;
constexpr int DV   = 256;
constexpr int COUT = 512;

// ---------------- scratch layout ----------------
constexpr size_t align256(size_t x) { return (x + 255) & ~(size_t)255; }
constexpr size_t SZ_XT     = (size_t)BB * HW * CIN * 2;          // [b][p][c] fp16
constexpr size_t SZ_WQKV   = (size_t)OQKV * CIN * 2;
constexpr size_t SZ_BQKV   = (size_t)OQKV * 4;
constexpr size_t SZ_WATTN  = (size_t)COUT * DV * 2;
constexpr size_t SZ_QT     = (size_t)BB * NH * HW * DH * 2;      // [z][p][d]
constexpr size_t SZ_KT     = SZ_QT;
constexpr size_t SZ_V      = SZ_QT;                              // [z][d][p]
constexpr size_t SZ_AFT    = (size_t)BB * HW * DV * 2;           // [b][p][c]

constexpr size_t OFF_XT    = 0;
constexpr size_t OFF_WQKV  = align256(OFF_XT    + SZ_XT);
constexpr size_t OFF_BQKV  = align256(OFF_WQKV  + SZ_WQKV);
constexpr size_t OFF_WATTN = align256(OFF_BQKV  + SZ_BQKV);
constexpr size_t OFF_QT    = align256(OFF_WATTN + SZ_WATTN);
constexpr size_t OFF_KT    = align256(OFF_QT    + SZ_QT);
constexpr size_t OFF_V     = align256(OFF_KT    + SZ_KT);
constexpr size_t OFF_AFT   = align256(OFF_V     + SZ_V);
constexpr size_t OFF_END   = align256(OFF_AFT   + SZ_AFT);

__device__ __align__(1024) unsigned char g_scratch[OFF_END];

// ---------------- mma / async helpers ----------------
DI uint32_t smem_u32(const void* p) { return (uint32_t)__cvta_generic_to_shared(p); }

DI void ldmx4(uint32_t* r, uint32_t a) {
    asm volatile("ldmatrix.sync.aligned.m8n8.x4.shared.b16 {%0,%1,%2,%3}, [%4];\n"
                 : "=r"(r[0]), "=r"(r[1]), "=r"(r[2]), "=r"(r[3]) : "r"(a));
}

DI void mma16816(float* c, const uint32_t* a, const uint32_t* b) {
    asm volatile(
        "mma.sync.aligned.m16n8k16.row.col.f32.f16.f16.f32 "
        "{%0,%1,%2,%3}, {%4,%5,%6,%7}, {%8,%9}, {%0,%1,%2,%3};\n"
        : "+f"(c[0]), "+f"(c[1]), "+f"(c[2]), "+f"(c[3])
        : "r"(a[0]), "r"(a[1]), "r"(a[2]), "r"(a[3]), "r"(b[0]), "r"(b[1]));
}

DI void cpasync16(void* dst, const void* src) {
    asm volatile("cp.async.cg.shared.global [%0], [%1], 16;\n"
                 :: "r"(smem_u32(dst)), "l"(src));
}
DI void cpcommit() { asm volatile("cp.async.commit_group;\n"); }
template <int N> DI void cpwait() { asm volatile("cp.async.wait_group %0;\n" :: "n"(N)); }

// ---------------- converts ----------------
__global__ void k_conv_wqkv(const float* __restrict__ w, const float* __restrict__ b,
                            __half* __restrict__ wh, float* __restrict__ bh) {
    int i = blockIdx.x * 256 + threadIdx.x;
    constexpr float SC = 0.17677669529663689f; // 32^-0.5 folded into q rows
    if (i < OQKV * CIN) wh[i] = __float2half(w[i] * (i < 256 * CIN ? SC : 1.f));
    if (i < OQKV)       bh[i] = b[i] * (i < 256 ? SC : 1.f);
}

__global__ void k_conv_wattn(const float* __restrict__ w, __half* __restrict__ wh) {
    int i = blockIdx.x * 256 + threadIdx.x;
    if (i < COUT * DV) wh[i] = __float2half(w[i]);
}

// x [b][c][p] fp32 -> XT [b][p][c] fp16  (tiled transpose)
__global__ void k_xT(const float* __restrict__ x, __half* __restrict__ xt) {
    __shared__ float t[32][33];
    int b = blockIdx.z, p0 = blockIdx.x * 32, c0 = blockIdx.y * 32;
    int tx = threadIdx.x, ty = threadIdx.y;
    const float* xp = x + ((long)b * CIN + c0) * HW + p0;
#pragma unroll
    for (int i = 0; i < 32; i += 8) t[ty + i][tx] = xp[(long)(ty + i) * HW + tx];
    __syncthreads();
    __half* d = xt + ((long)b * HW + p0) * CIN + c0;
#pragma unroll
    for (int i = 0; i < 32; i += 8) d[(long)(ty + i) * CIN + tx] = __float2half(t[tx][ty + i]);
}

// ---------------- templated HMMA GEMM (projections) ----------------
// C[m][n] = sum_k A[m][k] * B[n][k]
// EPI 1: qkv scatter (+bias, q/k -> [z][p][d], v -> [z][d][p])   EPI 3: fp32 + bias
template <int BM, int BN, int BK, int WM, int WN, int NT, int EPI>
__global__ void __launch_bounds__(NT) gemm_k(
    const __half* __restrict__ A, const __half* __restrict__ Bg,
    void* __restrict__ Cg, const float* __restrict__ bias,
    __half* __restrict__ aux1, __half* __restrict__ aux2,
    int K, int lda, int ldb, int ldc, long sA, long sB, long sC)
{
    constexpr int PAD = 8;
    __shared__ __half As[BM][BK + PAD];
    __shared__ __half Bs[BN][BK + PAD];

    const int z  = blockIdx.z;
    const int m0 = blockIdx.y * BM;
    const int n0 = blockIdx.x * BN;
    const __half* Ap = A  + (long)z * sA + (long)m0 * lda;
    const __half* Bp = Bg + (long)z * sB + (long)n0 * ldb;

    const int tid = threadIdx.x, lane = tid & 31, warp = tid >> 5;
    constexpr int WGM   = BM / WM;
    constexpr int MT    = WM / 16;
    constexpr int NTL   = WN / 8;
    const int wm = warp % WGM, wn = warp / WGM;

    float acc[MT][NTL][4];
#pragma unroll
    for (int a = 0; a < MT; a++)
#pragma unroll
        for (int b = 0; b < NTL; b++)
#pragma unroll
            for (int c = 0; c < 4; c++) acc[a][b][c] = 0.f;

    constexpr int KV = BK / 8;
    constexpr int AV = BM * BK / 8, BV = BN * BK / 8;

    for (int k0 = 0; k0 < K; k0 += BK) {
#pragma unroll
        for (int i = 0; i < AV / NT; i++) {
            int idx = tid + i * NT;
            int r = idx / KV, cv = idx % KV;
            *(uint4*)&As[r][cv * 8] = *(const uint4*)&Ap[(long)r * lda + k0 + cv * 8];
        }
#pragma unroll
        for (int i = 0; i < BV / NT; i++) {
            int idx = tid + i * NT;
            int r = idx / KV, cv = idx % KV;
            *(uint4*)&Bs[r][cv * 8] = *(const uint4*)&Bp[(long)r * ldb + k0 + cv * 8];
        }
        __syncthreads();
#pragma unroll
        for (int ks = 0; ks < BK; ks += 16) {
            uint32_t af[MT][4];
#pragma unroll
            for (int mt = 0; mt < MT; mt++)
                ldmx4(af[mt], smem_u32(&As[wm * WM + mt * 16 + (lane & 15)][ks + (lane >> 4) * 8]));
            uint32_t bf[NTL][2];
#pragma unroll
            for (int np = 0; np < NTL / 2; np++) {
                uint32_t r[4];
                ldmx4(r, smem_u32(&Bs[wn * WN + np * 16 + (lane & 15)][ks + (lane >> 4) * 8]));
                bf[np * 2][0] = r[0]; bf[np * 2][1] = r[2];
                bf[np * 2 + 1][0] = r[1]; bf[np * 2 + 1][1] = r[3];
            }
#pragma unroll
            for (int mt = 0; mt < MT; mt++)
#pragma unroll
                for (int nt = 0; nt < NTL; nt++)
                    mma16816(acc[mt][nt], af[mt], bf[nt]);
        }
        __syncthreads();
    }

#pragma unroll
    for (int mt = 0; mt < MT; mt++)
#pragma unroll
        for (int nt = 0; nt < NTL; nt++)
#pragma unroll
            for (int i = 0; i < 4; i++) {
                int m = m0 + wm * WM + mt * 16 + (lane >> 2) + ((i >> 1) << 3);
                int n = n0 + wn * WN + nt * 8 + ((lane & 3) << 1) + (i & 1);
                float v = acc[mt][nt][i];
                if constexpr (EPI == 1) {
                    v += bias[m];
                    int r = m >> 8, rr = m & 255, nh = rr >> 5, d = rr & 31;
                    __half hv = __float2half(v);
                    long zi = (long)(z * NH + nh);
                    if (r == 0)      ((__half*)Cg)[(zi * HW + n) * DH + d] = hv;  // qT
                    else if (r == 1) aux1[(zi * HW + n) * DH + d] = hv;           // kT
                    else             aux2[(zi * DH + d) * HW + n] = hv;           // v
                } else {
                    ((float*)Cg)[(long)z * sC + (long)m * ldc + n] = v + bias[m];
                }
            }
}

// ---------------- fused logits -> head-softmax -> attn ----------------
// Grid: (16 q-tiles, 8 batches), 512 threads = 16 warps, 2 warps per head.
// Per CTA: all 8 heads, 64 q rows, loop over 32-wide k tiles (32 iters).
constexpr int NIT = 32;

struct FusedSmem {
    __half Qs[8][64][40];       // [head][q][d+pad]
    __half Ks[2][8][32][40];    // [buf][head][kpos][d+pad]
    __half Vs[2][8][32][40];    // [buf][head][d][kpos+pad]
    __half Ls[8][64][40];       // [head][q][kpos+pad] logits/weights
};
static_assert(sizeof(FusedSmem) == 163840, "smem size");

__global__ void __launch_bounds__(512, 1) k_fused_attn(
    const __half* __restrict__ QT, const __half* __restrict__ KT,
    const __half* __restrict__ V, __half* __restrict__ AFT)
{
    extern __shared__ unsigned char smraw[];
    FusedSmem& sm = *reinterpret_cast<FusedSmem*>(smraw);
    const int b = blockIdx.y, qt = blockIdx.x;
    const int tid = threadIdx.x, lane = tid & 31, warp = tid >> 5;
    const int nh = warp >> 1, hf = warp & 1;
    const long zb = (long)b * NH;

    // resident Q tile: 512 rows (head, q), one row per thread (4x 16B)
    {
        int n = tid >> 6, q = tid & 63;
        const uint4* src = (const uint4*)(QT + ((zb + n) * HW + (long)qt * 64 + q) * DH);
        uint4* dst = (uint4*)&sm.Qs[n][q][0];
        dst[0] = src[0]; dst[1] = src[1]; dst[2] = src[2]; dst[3] = src[3];
    }

    auto loadKV = [&](int it, int buf) {
        int kp0 = it * 32;
#pragma unroll
        for (int i = 0; i < 2; i++) {
            int idx = tid + i * 512;
            int n = idx >> 7, kp = (idx >> 2) & 31, cv = idx & 3;
            cpasync16(&sm.Ks[buf][n][kp][cv * 8],
                      KT + ((zb + n) * HW + kp0 + kp) * DH + cv * 8);
        }
#pragma unroll
        for (int i = 0; i < 2; i++) {
            int idx = tid + i * 512;
            int n = idx >> 7, d = (idx >> 2) & 31, cv = idx & 3;
            cpasync16(&sm.Vs[buf][n][d][cv * 8],
                      V + ((zb + n) * DH + d) * HW + kp0 + cv * 8);
        }
        cpcommit();
    };
    loadKV(0, 0);

    float oacc[4][2][4];
#pragma unroll
    for (int a = 0; a < 4; a++)
#pragma unroll
        for (int c = 0; c < 2; c++)
#pragma unroll
            for (int i = 0; i < 4; i++) oacc[a][c][i] = 0.f;

    for (int it = 0; it < NIT; it++) {
        const int buf = it & 1;
        __syncthreads();   // prev-iter reads of Ls / K/V alt buffer complete
        if (it + 1 < NIT) { loadKV(it + 1, buf ^ 1); cpwait<1>(); }
        else              { cpwait<0>(); }
        __syncthreads();   // current K/V tile visible to all

        // ---- logits: C[q=64][k=16 (this warp's half of 32)] over d=32 ----
        float lacc[4][2][4];
#pragma unroll
        for (int a = 0; a < 4; a++)
#pragma unroll
            for (int c = 0; c < 2; c++)
#pragma unroll
                for (int i = 0; i < 4; i++) lacc[a][c][i] = 0.f;
#pragma unroll
        for (int ks = 0; ks < 32; ks += 16) {
            uint32_t af[4][4];
#pragma unroll
            for (int mt = 0; mt < 4; mt++)
                ldmx4(af[mt], smem_u32(&sm.Qs[nh][mt * 16 + (lane & 15)][ks + (lane >> 4) * 8]));
            uint32_t bf[2][2];
            {
                uint32_t r[4];
                ldmx4(r, smem_u32(&sm.Ks[buf][nh][hf * 16 + (lane & 15)][ks + (lane >> 4) * 8]));
                bf[0][0] = r[0]; bf[0][1] = r[2]; bf[1][0] = r[1]; bf[1][1] = r[3];
            }
#pragma unroll
            for (int mt = 0; mt < 4; mt++)
#pragma unroll
                for (int nt = 0; nt < 2; nt++)
                    mma16816(lacc[mt][nt], af[mt], bf[nt]);
        }
        // write fp16 logits to smem
#pragma unroll
        for (int mt = 0; mt < 4; mt++)
#pragma unroll
            for (int nt = 0; nt < 2; nt++) {
                int m = mt * 16 + (lane >> 2);
                int c = hf * 16 + nt * 8 + (lane & 3) * 2;
                *(__half2*)&sm.Ls[nh][m][c]     = __floats2half2_rn(lacc[mt][nt][0], lacc[mt][nt][1]);
                *(__half2*)&sm.Ls[nh][m + 8][c] = __floats2half2_rn(lacc[mt][nt][2], lacc[mt][nt][3]);
            }
        __syncthreads();

        // ---- softmax across the 8 heads (elementwise in (q,k)) ----
#pragma unroll
        for (int i = 0; i < 2; i++) {
            int idx = tid + i * 512;
            int q = idx >> 4, k2 = (idx & 15) * 2;
            float2 l[8];
            float m0 = -1e30f, m1 = -1e30f;
#pragma unroll
            for (int n = 0; n < 8; n++) {
                l[n] = __half22float2(*(__half2*)&sm.Ls[n][q][k2]);
                m0 = fmaxf(m0, l[n].x); m1 = fmaxf(m1, l[n].y);
            }
            float s0 = 0.f, s1 = 0.f;
#pragma unroll
            for (int n = 0; n < 8; n++) {
                l[n].x = __expf(l[n].x - m0); l[n].y = __expf(l[n].y - m1);
                s0 += l[n].x; s1 += l[n].y;
            }
            float r0 = __fdividef(1.f, s0), r1 = __fdividef(1.f, s1);
#pragma unroll
            for (int n = 0; n < 8; n++)
                *(__half2*)&sm.Ls[n][q][k2] = __floats2half2_rn(l[n].x * r0, l[n].y * r1);
        }
        __syncthreads();

        // ---- attn: oacc[q=64][d=16 (warp half)] += W[64x32] * V[32-k x d] ----
#pragma unroll
        for (int ks = 0; ks < 32; ks += 16) {
            uint32_t af[4][4];
#pragma unroll
            for (int mt = 0; mt < 4; mt++)
                ldmx4(af[mt], smem_u32(&sm.Ls[nh][mt * 16 + (lane & 15)][ks + (lane >> 4) * 8]));
            uint32_t bf[2][2];
            {
                uint32_t r[4];
                ldmx4(r, smem_u32(&sm.Vs[buf][nh][hf * 16 + (lane & 15)][ks + (lane >> 4) * 8]));
                bf[0][0] = r[0]; bf[0][1] = r[2]; bf[1][0] = r[1]; bf[1][1] = r[3];
            }
#pragma unroll
            for (int mt = 0; mt < 4; mt++)
#pragma unroll
                for (int nt = 0; nt < 2; nt++)
                    mma16816(oacc[mt][nt], af[mt], bf[nt]);
        }
    }

    // epilogue: reshape-scramble scatter -> AFT[b][p][c] fp16
    const long obase = (long)b * HW * DV;
#pragma unroll
    for (int mt = 0; mt < 4; mt++)
#pragma unroll
        for (int nt = 0; nt < 2; nt++)
#pragma unroll
            for (int i = 0; i < 4; i++) {
                int m = qt * 64 + mt * 16 + (lane >> 2) + ((i >> 1) << 3);
                int d = hf * 16 + nt * 8 + ((lane & 3) << 1) + (i & 1);
                int j = m * DH + d;
                int c2 = j >> 10, p = j & 1023;
                AFT[obase + (long)p * DV + nh * DH + c2] = __float2half(oacc[mt][nt][i]);
            }
}

// ---------------- launch ----------------
extern "C" void kernel_launch(void* const* d_in, const int* in_sizes, int n_in,
                              void* d_out, int out_size)
{
    const float* x      = (const float*)d_in[0];
    const float* w_qkv  = (const float*)d_in[1];
    const float* b_qkv  = (const float*)d_in[2];
    const float* w_attn = (const float*)d_in[3];
    const float* b_attn = (const float*)d_in[4];
    float* out = (float*)d_out;

    unsigned char* s = nullptr;
    cudaGetSymbolAddress((void**)&s, g_scratch);
    __half* XT    = (__half*)(s + OFF_XT);
    __half* WQKV  = (__half*)(s + OFF_WQKV);
    float*  BQKV  = (float*) (s + OFF_BQKV);
    __half* WATTN = (__half*)(s + OFF_WATTN);
    __half* QT    = (__half*)(s + OFF_QT);
    __half* KT    = (__half*)(s + OFF_KT);
    __half* V     = (__half*)(s + OFF_V);
    __half* AFT   = (__half*)(s + OFF_AFT);

    // converts
    k_conv_wqkv <<<(OQKV * CIN + 255) / 256, 256>>>(w_qkv, b_qkv, WQKV, BQKV);
    k_conv_wattn<<<(COUT * DV + 255) / 256, 256>>>(w_attn, WATTN);
    k_xT<<<dim3(HW / 32, CIN / 32, BB), dim3(32, 8)>>>(x, XT);

    // QKV: per b, [768x512] x [512x1024]; scatter q/k/v (+bias, q-scale folded)
    gemm_k<128, 128, 32, 64, 32, 256, 1><<<dim3(HW / 128, OQKV / 128, BB), 256>>>(
        WQKV, XT, QT, BQKV, KT, V, CIN, CIN, CIN, 0, 0L, (long)HW * CIN, 0L);

    // fused logits -> head softmax -> attn -> scrambled AFT
    cudaFuncSetAttribute(k_fused_attn, cudaFuncAttributeMaxDynamicSharedMemorySize,
                         (int)sizeof(FusedSmem));
    k_fused_attn<<<dim3(HW / 64, BB), 512, sizeof(FusedSmem)>>>(QT, KT, V, AFT);

    // output projection: per b, [512x256] x [256x1024] + bias -> fp32
    gemm_k<128, 128, 32, 64, 32, 256, 3><<<dim3(HW / 128, COUT / 128, BB), 256>>>(
        WATTN, AFT, out, b_attn, nullptr, nullptr, DV, DV, DV, HW,
        0L, (long)HW * DV, (long)COUT * HW);
}

// round 4
// speedup vs baseline: 1.8170x; 1.0083x over previous
#include <cuda_runtime.h>
#include <cuda_fp16.h>
#include <cstdint>

#define DI __device__ __forceinline__

// ---------------- problem dims ----------------
constexpr int BB   = 8;
constexpr int CIN  = 512;
constexpr int HW   = 1024;
constexpr int NH   = 8;
constexpr int DH   = 32;    // head dim
constexpr int OQKV = 768;
constexpr int DV   = 256;
constexpr int COUT = 512;

// ---------------- scratch layout ----------------
constexpr size_t align256(size_t x) { return (x + 255) & ~(size_t)255; }
constexpr size_t SZ_XT     = (size_t)BB * HW * CIN * 2;          // [b][p][c] fp16
constexpr size_t SZ_WQKV   = (size_t)OQKV * CIN * 2;
constexpr size_t SZ_BQKV   = (size_t)OQKV * 4;
constexpr size_t SZ_WATTN  = (size_t)COUT * DV * 2;
constexpr size_t SZ_QT     = (size_t)BB * NH * HW * DH * 2;      // [z][p][d]
constexpr size_t SZ_KT     = SZ_QT;
constexpr size_t SZ_V      = SZ_QT;                              // [z][d][p]
constexpr size_t SZ_AFT    = (size_t)BB * HW * DV * 2;           // [b][p][c]

constexpr size_t OFF_XT    = 0;
constexpr size_t OFF_WQKV  = align256(OFF_XT    + SZ_XT);
constexpr size_t OFF_BQKV  = align256(OFF_WQKV  + SZ_WQKV);
constexpr size_t OFF_WATTN = align256(OFF_BQKV  + SZ_BQKV);
constexpr size_t OFF_QT    = align256(OFF_WATTN + SZ_WATTN);
constexpr size_t OFF_KT    = align256(OFF_QT    + SZ_QT);
constexpr size_t OFF_V     = align256(OFF_KT    + SZ_KT);
constexpr size_t OFF_AFT   = align256(OFF_V     + SZ_V);
constexpr size_t OFF_END   = align256(OFF_AFT   + SZ_AFT);

__device__ __align__(1024) unsigned char g_scratch[OFF_END];

// ---------------- mma / async helpers ----------------
DI uint32_t smem_u32(const void* p) { return (uint32_t)__cvta_generic_to_shared(p); }

DI void ldmx4(uint32_t* r, uint32_t a) {
    asm volatile("ldmatrix.sync.aligned.m8n8.x4.shared.b16 {%0,%1,%2,%3}, [%4];\n"
                 : "=r"(r[0]), "=r"(r[1]), "=r"(r[2]), "=r"(r[3]) : "r"(a));
}

DI void mma16816(float* c, const uint32_t* a, const uint32_t* b) {
    asm volatile(
        "mma.sync.aligned.m16n8k16.row.col.f32.f16.f16.f32 "
        "{%0,%1,%2,%3}, {%4,%5,%6,%7}, {%8,%9}, {%0,%1,%2,%3};\n"
        : "+f"(c[0]), "+f"(c[1]), "+f"(c[2]), "+f"(c[3])
        : "r"(a[0]), "r"(a[1]), "r"(a[2]), "r"(a[3]), "r"(b[0]), "r"(b[1]));
}

DI void cpasync16(void* dst, const void* src) {
    asm volatile("cp.async.cg.shared.global [%0], [%1], 16;\n"
                 :: "r"(smem_u32(dst)), "l"(src));
}
DI void cpcommit() { asm volatile("cp.async.commit_group;\n"); }
template <int N> DI void cpwait() { asm volatile("cp.async.wait_group %0;\n" :: "n"(N)); }

// ---------------- converts ----------------
__global__ void k_conv_wqkv(const float* __restrict__ w, const float* __restrict__ b,
                            __half* __restrict__ wh, float* __restrict__ bh) {
    int i = blockIdx.x * 256 + threadIdx.x;
    constexpr float SC = 0.17677669529663689f; // 32^-0.5 folded into q rows
    if (i < OQKV * CIN) wh[i] = __float2half(w[i] * (i < 256 * CIN ? SC : 1.f));
    if (i < OQKV)       bh[i] = b[i] * (i < 256 ? SC : 1.f);
}

__global__ void k_conv_wattn(const float* __restrict__ w, __half* __restrict__ wh) {
    int i = blockIdx.x * 256 + threadIdx.x;
    if (i < COUT * DV) wh[i] = __float2half(w[i]);
}

// x [b][c][p] fp32 -> XT [b][p][c] fp16  (tiled transpose)
__global__ void k_xT(const float* __restrict__ x, __half* __restrict__ xt) {
    __shared__ float t[32][33];
    int b = blockIdx.z, p0 = blockIdx.x * 32, c0 = blockIdx.y * 32;
    int tx = threadIdx.x, ty = threadIdx.y;
    const float* xp = x + ((long)b * CIN + c0) * HW + p0;
#pragma unroll
    for (int i = 0; i < 32; i += 8) t[ty + i][tx] = xp[(long)(ty + i) * HW + tx];
    __syncthreads();
    __half* d = xt + ((long)b * HW + p0) * CIN + c0;
#pragma unroll
    for (int i = 0; i < 32; i += 8) d[(long)(ty + i) * CIN + tx] = __float2half(t[tx][ty + i]);
}

// ---------------- cp.async double-buffered HMMA GEMM (projections) ----------------
// C[m][n] = sum_k A[m][k] * B[n][k]
// EPI 1: qkv scatter (+bias, q/k -> [z][p][d], v -> [z][d][p])   EPI 3: fp32 + bias
template <int BM, int BN, int BK, int WM, int WN, int NT, int EPI>
__global__ void __launch_bounds__(NT) gemm_k(
    const __half* __restrict__ A, const __half* __restrict__ Bg,
    void* __restrict__ Cg, const float* __restrict__ bias,
    __half* __restrict__ aux1, __half* __restrict__ aux2,
    int K, int lda, int ldb, int ldc, long sA, long sB, long sC)
{
    constexpr int PAD = 8;
    __shared__ __half As[2][BM][BK + PAD];
    __shared__ __half Bs[2][BN][BK + PAD];

    const int z  = blockIdx.z;
    const int m0 = blockIdx.y * BM;
    const int n0 = blockIdx.x * BN;
    const __half* Ap = A  + (long)z * sA + (long)m0 * lda;
    const __half* Bp = Bg + (long)z * sB + (long)n0 * ldb;

    const int tid = threadIdx.x, lane = tid & 31, warp = tid >> 5;
    constexpr int WGM   = BM / WM;
    constexpr int MT    = WM / 16;
    constexpr int NTL   = WN / 8;
    const int wm = warp % WGM, wn = warp / WGM;

    float acc[MT][NTL][4];
#pragma unroll
    for (int a = 0; a < MT; a++)
#pragma unroll
        for (int b = 0; b < NTL; b++)
#pragma unroll
            for (int c = 0; c < 4; c++) acc[a][b][c] = 0.f;

    constexpr int KV = BK / 8;
    constexpr int AV = BM * BK / 8, BV = BN * BK / 8;

    auto loadT = [&](int k0, int s) {
#pragma unroll
        for (int i = 0; i < AV / NT; i++) {
            int idx = tid + i * NT;
            int r = idx / KV, cv = idx % KV;
            cpasync16(&As[s][r][cv * 8], &Ap[(long)r * lda + k0 + cv * 8]);
        }
#pragma unroll
        for (int i = 0; i < BV / NT; i++) {
            int idx = tid + i * NT;
            int r = idx / KV, cv = idx % KV;
            cpasync16(&Bs[s][r][cv * 8], &Bp[(long)r * ldb + k0 + cv * 8]);
        }
        cpcommit();
    };

    const int NK = K / BK;
    loadT(0, 0);

    for (int it = 0; it < NK; it++) {
        const int s = it & 1;
        cpwait<0>();
        __syncthreads();               // tile(it) visible; prev compute done
        if (it + 1 < NK) loadT((it + 1) * BK, s ^ 1);
#pragma unroll
        for (int ks = 0; ks < BK; ks += 16) {
            uint32_t af[MT][4];
#pragma unroll
            for (int mt = 0; mt < MT; mt++)
                ldmx4(af[mt], smem_u32(&As[s][wm * WM + mt * 16 + (lane & 15)][ks + (lane >> 4) * 8]));
            uint32_t bf[NTL][2];
#pragma unroll
            for (int np = 0; np < NTL / 2; np++) {
                uint32_t r[4];
                ldmx4(r, smem_u32(&Bs[s][wn * WN + np * 16 + (lane & 15)][ks + (lane >> 4) * 8]));
                bf[np * 2][0] = r[0]; bf[np * 2][1] = r[2];
                bf[np * 2 + 1][0] = r[1]; bf[np * 2 + 1][1] = r[3];
            }
#pragma unroll
            for (int mt = 0; mt < MT; mt++)
#pragma unroll
                for (int nt = 0; nt < NTL; nt++)
                    mma16816(acc[mt][nt], af[mt], bf[nt]);
        }
    }

#pragma unroll
    for (int mt = 0; mt < MT; mt++)
#pragma unroll
        for (int nt = 0; nt < NTL; nt++)
#pragma unroll
            for (int i = 0; i < 4; i++) {
                int m = m0 + wm * WM + mt * 16 + (lane >> 2) + ((i >> 1) << 3);
                int n = n0 + wn * WN + nt * 8 + ((lane & 3) << 1) + (i & 1);
                float v = acc[mt][nt][i];
                if constexpr (EPI == 1) {
                    v += bias[m];
                    int r = m >> 8, rr = m & 255, nh = rr >> 5, d = rr & 31;
                    __half hv = __float2half(v);
                    long zi = (long)(z * NH + nh);
                    if (r == 0)      ((__half*)Cg)[(zi * HW + n) * DH + d] = hv;  // qT
                    else if (r == 1) aux1[(zi * HW + n) * DH + d] = hv;           // kT
                    else             aux2[(zi * DH + d) * HW + n] = hv;           // v
                } else {
                    ((float*)Cg)[(long)z * sC + (long)m * ldc + n] = v + bias[m];
                }
            }
}

// ---------------- fused logits -> head-softmax -> attn ----------------
// Grid: (16 q-tiles, 8 batches), 512 threads = 16 warps.
// Logits phase: warp = (qg 0..3) x (kg 0..3); each warp computes a q16 x k8
//   patch for ALL 8 heads -> per-thread registers hold the full head axis at
//   each (q,k) position -> softmax is thread-local fp32, weights written once.
// Attn phase: warp = (head, d-half) as before, reads weights via ldmatrix.
constexpr int NIT = 32;

struct FusedSmem {
    __half Qs[8][64][40];       // [head][q][d+pad]
    __half Ks[2][8][32][40];    // [buf][head][kpos][d+pad]
    __half Vs[2][8][32][40];    // [buf][head][d][kpos+pad]
    __half Ws[8][64][40];       // [head][q][kpos+pad] softmaxed weights
};
static_assert(sizeof(FusedSmem) == 163840, "smem size");

__global__ void __launch_bounds__(512, 1) k_fused_attn(
    const __half* __restrict__ QT, const __half* __restrict__ KT,
    const __half* __restrict__ V, __half* __restrict__ AFT)
{
    extern __shared__ unsigned char smraw[];
    FusedSmem& sm = *reinterpret_cast<FusedSmem*>(smraw);
    const int b = blockIdx.y, qt = blockIdx.x;
    const int tid = threadIdx.x, lane = tid & 31, warp = tid >> 5;
    const int qg = warp & 3, kg = warp >> 2;        // logits mapping
    const int nh = warp >> 1, hf = warp & 1;        // attn mapping
    const long zb = (long)b * NH;

    // resident Q tile: 512 rows (head, q), one row per thread (4x 16B)
    {
        int n = tid >> 6, q = tid & 63;
        const uint4* src = (const uint4*)(QT + ((zb + n) * HW + (long)qt * 64 + q) * DH);
        uint4* dst = (uint4*)&sm.Qs[n][q][0];
        dst[0] = src[0]; dst[1] = src[1]; dst[2] = src[2]; dst[3] = src[3];
    }

    auto loadKV = [&](int it, int buf) {
        int kp0 = it * 32;
#pragma unroll
        for (int i = 0; i < 2; i++) {
            int idx = tid + i * 512;
            int n = idx >> 7, kp = (idx >> 2) & 31, cv = idx & 3;
            cpasync16(&sm.Ks[buf][n][kp][cv * 8],
                      KT + ((zb + n) * HW + kp0 + kp) * DH + cv * 8);
        }
#pragma unroll
        for (int i = 0; i < 2; i++) {
            int idx = tid + i * 512;
            int n = idx >> 7, d = (idx >> 2) & 31, cv = idx & 3;
            cpasync16(&sm.Vs[buf][n][d][cv * 8],
                      V + ((zb + n) * DH + d) * HW + kp0 + cv * 8);
        }
        cpcommit();
    };
    loadKV(0, 0);

    float oacc[4][2][4];
#pragma unroll
    for (int a = 0; a < 4; a++)
#pragma unroll
        for (int c = 0; c < 2; c++)
#pragma unroll
            for (int i = 0; i < 4; i++) oacc[a][c][i] = 0.f;

    // logits-phase smem addresses (loop-invariant parts)
    const int arow = qg * 16 + (lane & 15);
    const int krow = kg * 8 + (lane & 7);
    const int kcol = (lane >> 3) * 8;
    const int wrow = qg * 16 + (lane >> 2);
    const int wcol = kg * 8 + (lane & 3) * 2;

    for (int it = 0; it < NIT; it++) {
        const int buf = it & 1;
        cpwait<0>();
        __syncthreads();   // KV(it) visible; prev-iter attn done (Ws / alt bufs free)
        if (it + 1 < NIT) loadKV(it + 1, buf ^ 1);

        // ---- logits for all 8 heads: q16 x k8 patch per warp ----
        float lacc[8][4];
#pragma unroll
        for (int h = 0; h < 8; h++) {
            lacc[h][0] = lacc[h][1] = lacc[h][2] = lacc[h][3] = 0.f;
            uint32_t a0[4], a1[4], kr[4];
            ldmx4(a0, smem_u32(&sm.Qs[h][arow][(lane >> 4) * 8]));
            ldmx4(a1, smem_u32(&sm.Qs[h][arow][16 + (lane >> 4) * 8]));
            ldmx4(kr, smem_u32(&sm.Ks[buf][h][krow][kcol]));
            mma16816(lacc[h], a0, &kr[0]);   // d 0..15
            mma16816(lacc[h], a1, &kr[2]);   // d 16..31
        }

        // ---- thread-local softmax over the head axis (4 (q,k) positions) ----
        float mx0 = lacc[0][0], mx1 = lacc[0][1], mx2 = lacc[0][2], mx3 = lacc[0][3];
#pragma unroll
        for (int h = 1; h < 8; h++) {
            mx0 = fmaxf(mx0, lacc[h][0]); mx1 = fmaxf(mx1, lacc[h][1]);
            mx2 = fmaxf(mx2, lacc[h][2]); mx3 = fmaxf(mx3, lacc[h][3]);
        }
        float s0 = 0.f, s1 = 0.f, s2 = 0.f, s3 = 0.f;
#pragma unroll
        for (int h = 0; h < 8; h++) {
            lacc[h][0] = __expf(lacc[h][0] - mx0); s0 += lacc[h][0];
            lacc[h][1] = __expf(lacc[h][1] - mx1); s1 += lacc[h][1];
            lacc[h][2] = __expf(lacc[h][2] - mx2); s2 += lacc[h][2];
            lacc[h][3] = __expf(lacc[h][3] - mx3); s3 += lacc[h][3];
        }
        float r0 = __fdividef(1.f, s0), r1 = __fdividef(1.f, s1);
        float r2 = __fdividef(1.f, s2), r3 = __fdividef(1.f, s3);
#pragma unroll
        for (int h = 0; h < 8; h++) {
            *(__half2*)&sm.Ws[h][wrow][wcol]     = __floats2half2_rn(lacc[h][0] * r0, lacc[h][1] * r1);
            *(__half2*)&sm.Ws[h][wrow + 8][wcol] = __floats2half2_rn(lacc[h][2] * r2, lacc[h][3] * r3);
        }
        __syncthreads();   // weights visible

        // ---- attn: oacc[q=64][d=16 (warp half)] += W[64x32] * V[32-k x d] ----
#pragma unroll
        for (int ks = 0; ks < 32; ks += 16) {
            uint32_t af[4][4];
#pragma unroll
            for (int mt = 0; mt < 4; mt++)
                ldmx4(af[mt], smem_u32(&sm.Ws[nh][mt * 16 + (lane & 15)][ks + (lane >> 4) * 8]));
            uint32_t bf[2][2];
            {
                uint32_t r[4];
                ldmx4(r, smem_u32(&sm.Vs[buf][nh][hf * 16 + (lane & 15)][ks + (lane >> 4) * 8]));
                bf[0][0] = r[0]; bf[0][1] = r[2]; bf[1][0] = r[1]; bf[1][1] = r[3];
            }
#pragma unroll
            for (int mt = 0; mt < 4; mt++)
#pragma unroll
                for (int nt = 0; nt < 2; nt++)
                    mma16816(oacc[mt][nt], af[mt], bf[nt]);
        }
    }

    // epilogue: reshape-scramble scatter -> AFT[b][p][c] fp16
    const long obase = (long)b * HW * DV;
#pragma unroll
    for (int mt = 0; mt < 4; mt++)
#pragma unroll
        for (int nt = 0; nt < 2; nt++)
#pragma unroll
            for (int i = 0; i < 4; i++) {
                int m = qt * 64 + mt * 16 + (lane >> 2) + ((i >> 1) << 3);
                int d = hf * 16 + nt * 8 + ((lane & 3) << 1) + (i & 1);
                int j = m * DH + d;
                int c2 = j >> 10, p = j & 1023;
                AFT[obase + (long)p * DV + nh * DH + c2] = __float2half(oacc[mt][nt][i]);
            }
}

// ---------------- launch ----------------
extern "C" void kernel_launch(void* const* d_in, const int* in_sizes, int n_in,
                              void* d_out, int out_size)
{
    const float* x      = (const float*)d_in[0];
    const float* w_qkv  = (const float*)d_in[1];
    const float* b_qkv  = (const float*)d_in[2];
    const float* w_attn = (const float*)d_in[3];
    const float* b_attn = (const float*)d_in[4];
    float* out = (float*)d_out;

    unsigned char* s = nullptr;
    cudaGetSymbolAddress((void**)&s, g_scratch);
    __half* XT    = (__half*)(s + OFF_XT);
    __half* WQKV  = (__half*)(s + OFF_WQKV);
    float*  BQKV  = (float*) (s + OFF_BQKV);
    __half* WATTN = (__half*)(s + OFF_WATTN);
    __half* QT    = (__half*)(s + OFF_QT);
    __half* KT    = (__half*)(s + OFF_KT);
    __half* V     = (__half*)(s + OFF_V);
    __half* AFT   = (__half*)(s + OFF_AFT);

    // converts
    k_conv_wqkv <<<(OQKV * CIN + 255) / 256, 256>>>(w_qkv, b_qkv, WQKV, BQKV);
    k_conv_wattn<<<(COUT * DV + 255) / 256, 256>>>(w_attn, WATTN);
    k_xT<<<dim3(HW / 32, CIN / 32, BB), dim3(32, 8)>>>(x, XT);

    // QKV: per b, [768x512] x [512x1024]; scatter q/k/v (+bias, q-scale folded)
    gemm_k<128, 128, 32, 64, 32, 256, 1><<<dim3(HW / 128, OQKV / 128, BB), 256>>>(
        WQKV, XT, QT, BQKV, KT, V, CIN, CIN, CIN, 0, 0L, (long)HW * CIN, 0L);

    // fused logits -> head softmax -> attn -> scrambled AFT
    cudaFuncSetAttribute(k_fused_attn, cudaFuncAttributeMaxDynamicSharedMemorySize,
                         (int)sizeof(FusedSmem));
    k_fused_attn<<<dim3(HW / 64, BB), 512, sizeof(FusedSmem)>>>(QT, KT, V, AFT);

    // output projection: per b, [512x256] x [256x1024] + bias -> fp32
    gemm_k<128, 128, 32, 64, 32, 256, 3><<<dim3(HW / 128, COUT / 128, BB), 256>>>(
        WATTN, AFT, out, b_attn, nullptr, nullptr, DV, DV, DV, HW,
        0L, (long)HW * DV, (long)COUT * HW);
}